// round 15
// baseline (speedup 1.0000x reference)
#include <cuda_runtime.h>
#include <cuda_fp16.h>
#include <math.h>
#include <stdint.h>

#define HWN 9216
#define CCH 512
#define NG  32
#define CPG 16

typedef __half fp16;

// ---- scratch (static device globals) ----
__device__ fp16  g_s [(size_t)HWN * HWN];          // P = exp(scores), fp16 (170 MB)
__device__ fp16  g_hn[(size_t)HWN * CCH];
__device__ fp16  g_q [(size_t)HWN * CCH];
__device__ fp16  g_k [(size_t)HWN * CCH];
__device__ fp16  g_v [(size_t)CCH * HWN];          // v, [C, HW]
__device__ fp16  g_o [(size_t)HWN * CCH];
__device__ fp16  g_qw[CCH * CCH], g_kw[CCH * CCH];
__device__ fp16  g_vw[CCH * CCH], g_pw[CCH * CCH];
__device__ float g_rowpart[36 * HWN];
__device__ float g_stats[NG * 2];

// ---------------------------------------------------------------------------
// helpers
// ---------------------------------------------------------------------------
__device__ __forceinline__ uint32_t smem_u32(const void* p) {
    uint32_t a;
    asm("{ .reg .u64 t; cvta.to.shared.u64 t, %1; cvt.u32.u64 %0, t; }" : "=r"(a) : "l"(p));
    return a;
}
#define SWZ(x) ((x) ^ (((x) >> 3) & 0x70))

__device__ __forceinline__ void cp_async16(uint32_t saddr, const void* gaddr) {
    asm volatile("cp.async.cg.shared.global [%0], [%1], 16;" :: "r"(saddr), "l"(gaddr));
}
__device__ __forceinline__ void cp_commit() { asm volatile("cp.async.commit_group;"); }
#define CP_WAIT1() asm volatile("cp.async.wait_group 1;")
#define CP_WAIT2() asm volatile("cp.async.wait_group 2;")

__device__ __forceinline__ void ldm_x4(uint32_t* r, uint32_t addr) {
    asm volatile("ldmatrix.sync.aligned.m8n8.x4.shared.b16 {%0,%1,%2,%3}, [%4];"
                 : "=r"(r[0]), "=r"(r[1]), "=r"(r[2]), "=r"(r[3]) : "r"(addr));
}
__device__ __forceinline__ void mma16816(float* d, const uint32_t* a, uint32_t b0, uint32_t b1) {
    asm volatile(
        "mma.sync.aligned.m16n8k16.row.col.f32.f16.f16.f32 "
        "{%0,%1,%2,%3}, {%4,%5,%6,%7}, {%8,%9}, {%0,%1,%2,%3};"
        : "+f"(d[0]), "+f"(d[1]), "+f"(d[2]), "+f"(d[3])
        : "r"(a[0]), "r"(a[1]), "r"(a[2]), "r"(a[3]), "r"(b0), "r"(b1));
}
// fp16-accumulate variant (2 c/d regs = 4 halves, same thread->element map)
__device__ __forceinline__ void mma16816h(uint32_t* d, const uint32_t* a, uint32_t b0, uint32_t b1) {
    asm volatile(
        "mma.sync.aligned.m16n8k16.row.col.f16.f16.f16.f16 "
        "{%0,%1}, {%2,%3,%4,%5}, {%6,%7}, {%0,%1};"
        : "+r"(d[0]), "+r"(d[1])
        : "r"(a[0]), "r"(a[1]), "r"(a[2]), "r"(a[3]), "r"(b0), "r"(b1));
}

__device__ __forceinline__ uint32_t pack_h2(float a, float b) {
    __half2 h = __floats2half2_rn(a, b);
    return *(uint32_t*)&h;
}
__device__ __forceinline__ float2 h2f2(uint32_t u) {
    return __half22float2(*(__half2*)&u);
}

// ---------------------------------------------------------------------------
// GroupNorm stats
// ---------------------------------------------------------------------------
__global__ void gn_stats_kernel(const float* __restrict__ x) {
    const int g = blockIdx.x;
    const float4* xp = (const float4*)(x + (size_t)g * CPG * HWN);
    const int n4 = (CPG * HWN) / 4;
    float s = 0.f, s2 = 0.f;
    for (int i = threadIdx.x; i < n4; i += 256) {
        float4 v = xp[i];
        s  += v.x + v.y + v.z + v.w;
        s2 += v.x * v.x + v.y * v.y + v.z * v.z + v.w * v.w;
    }
    __shared__ float rs[256], rq[256];
    rs[threadIdx.x] = s; rq[threadIdx.x] = s2;
    __syncthreads();
    for (int o = 128; o > 0; o >>= 1) {
        if (threadIdx.x < o) {
            rs[threadIdx.x] += rs[threadIdx.x + o];
            rq[threadIdx.x] += rq[threadIdx.x + o];
        }
        __syncthreads();
    }
    if (threadIdx.x == 0) {
        const float inv  = 1.0f / (float)(CPG * HWN);
        const float mean = rs[0] * inv;
        const float var  = rq[0] * inv - mean * mean;
        g_stats[2 * g]     = mean;
        g_stats[2 * g + 1] = rsqrtf(var + 1e-6f);
    }
}

// ---------------------------------------------------------------------------
// GroupNorm apply + transpose: x [C, HW] -> hn fp16 [HW, C]
// ---------------------------------------------------------------------------
__global__ void gn_apply_t_kernel(const float* __restrict__ x,
                                  const float* __restrict__ gamma,
                                  const float* __restrict__ beta,
                                  fp16* __restrict__ out) {
    __shared__ float t[32][33];
    const int i0 = blockIdx.x * 32, c0 = blockIdx.y * 32;
    const int tx = threadIdx.x, ty = threadIdx.y;
#pragma unroll
    for (int k = 0; k < 32; k += 8) {
        const int c = c0 + ty + k;
        const int g = c >> 4;
        const float mean = g_stats[2 * g], rstd = g_stats[2 * g + 1];
        const float ga = gamma[c] * rstd;
        const float be = beta[c] - mean * ga;
        t[ty + k][tx] = x[(size_t)c * HWN + i0 + tx] * ga + be;
    }
    __syncthreads();
#pragma unroll
    for (int k = 0; k < 32; k += 8)
        out[(size_t)(i0 + ty + k) * CCH + c0 + tx] = __float2half(t[tx][ty + k]);
}

__global__ void cvt_all_kernel(const float* __restrict__ w0, fp16* __restrict__ h0,
                               const float* __restrict__ w1, fp16* __restrict__ h1,
                               const float* __restrict__ w2, fp16* __restrict__ h2,
                               const float* __restrict__ w3, fp16* __restrict__ h3) {
    const int i = blockIdx.x * 256 + threadIdx.x;
    h0[i] = __float2half(w0[i]);
    h1[i] = __float2half(w1[i]);
    h2[i] = __float2half(w2[i]);
    h3[i] = __float2half(w3[i]);
}

// ---------------------------------------------------------------------------
// Staging helper (narrow GEMMs): 128 rows x 64 halves per operand
// ---------------------------------------------------------------------------
#define STG_A(s) ((s) * 16384)
#define STG_B(s) (49152 + (s) * 16384)
#define GEMM_SMEM 98304

__device__ __forceinline__ void load_stage(
    uint32_t sbA, uint32_t sbB,
    const fp16* __restrict__ Ap, const fp16* __restrict__ Bp,
    int bm, int bn, int lda, int ldb, int k0, int tid)
{
#pragma unroll
    for (int r = 0; r < 4; r++) {
        const int idx = tid + (r << 8);
        const int row = idx >> 3, c8 = idx & 7;
        const uint32_t off = SWZ((row << 7) + (c8 << 4));
        cp_async16(sbA + off, Ap + (size_t)(bm + row) * lda + k0 + (c8 << 3));
        cp_async16(sbB + off, Bp + (size_t)(bn + row) * ldb + k0 + (c8 << 3));
    }
}

// ---------------------------------------------------------------------------
// Fused QKV GEMM (one launch, grid (4,72,3))
// ---------------------------------------------------------------------------
__global__ void __launch_bounds__(256, 2) gemm_qkv(
    const fp16* __restrict__ hn,
    const fp16* __restrict__ qwh, const fp16* __restrict__ kwh, const fp16* __restrict__ vwh,
    const float* __restrict__ qb, const float* __restrict__ kb, const float* __restrict__ vb,
    fp16* __restrict__ q, fp16* __restrict__ k, fp16* __restrict__ v)
{
    const int z = blockIdx.z;
    const bool isV = (z == 2);
    const fp16* A = isV ? vwh : hn;
    const fp16* B = isV ? hn : (z ? kwh : qwh);
    const float* bias = isV ? vb : (z ? kb : qb);
    fp16* Ch = isV ? v : (z ? k : q);
    const int ldc = isV ? HWN : CCH;
    const int bm = (isV ? blockIdx.x : blockIdx.y) * 128;
    const int bn = (isV ? blockIdx.y : blockIdx.x) * 128;

    extern __shared__ char smem[];
    const uint32_t sb = smem_u32(smem);
    const int tid  = threadIdx.x;
    const int lane = tid & 31, warp = tid >> 5;
    const int wm = (warp >> 2) * 64;
    const int wn = (warp & 3) * 32;

    float acc[4][4][4];
#pragma unroll
    for (int i = 0; i < 4; i++)
#pragma unroll
        for (int j = 0; j < 4; j++) {
            acc[i][j][0] = 0.f; acc[i][j][1] = 0.f;
            acc[i][j][2] = 0.f; acc[i][j][3] = 0.f;
        }

    const int NCH = CCH >> 6;   // 8
    load_stage(sb + STG_A(0), sb + STG_B(0), A, B, bm, bn, CCH, CCH, 0,  tid);
    cp_commit();
    load_stage(sb + STG_A(1), sb + STG_B(1), A, B, bm, bn, CCH, CCH, 64, tid);
    cp_commit();

    const int lr  = lane & 7;
    const int sel = lane >> 3;
    const int a_row  = wm + lr + (sel & 1) * 8;
    const int a_kb   = (sel >> 1) * 16;
    const int b_row0 = wn + lr + ((sel >> 1) & 1) * 8;
    const int b_kb   = (sel & 1) * 16;

#pragma unroll 1
    for (int c = 0; c < NCH; ++c) {
        CP_WAIT1();
        __syncthreads();
        const int cn = c + 2;
        if (cn < NCH)
            load_stage(sb + STG_A(cn % 3), sb + STG_B(cn % 3), A, B,
                       bm, bn, CCH, CCH, cn << 6, tid);
        cp_commit();

        const uint32_t sA = sb + STG_A(c % 3);
        const uint32_t sB = sb + STG_B(c % 3);
#pragma unroll
        for (int kk = 0; kk < 4; ++kk) {
            uint32_t af[4][4], bfr[2][4];
#pragma unroll
            for (int mi = 0; mi < 4; ++mi)
                ldm_x4(af[mi], sA + SWZ(((a_row + mi * 16) << 7) + kk * 32 + a_kb));
#pragma unroll
            for (int nj = 0; nj < 2; ++nj)
                ldm_x4(bfr[nj], sB + SWZ(((b_row0 + nj * 16) << 7) + kk * 32 + b_kb));
#pragma unroll
            for (int mi = 0; mi < 4; ++mi)
#pragma unroll
                for (int nj = 0; nj < 4; ++nj)
                    mma16816(acc[mi][nj], af[mi],
                             bfr[nj >> 1][(nj & 1) * 2], bfr[nj >> 1][(nj & 1) * 2 + 1]);
        }
    }

#pragma unroll
    for (int mi = 0; mi < 4; ++mi) {
#pragma unroll
        for (int nj = 0; nj < 4; ++nj) {
            const int r0 = bm + wm + mi * 16 + (lane >> 2);
            const int c0 = bn + wn + nj * 8 + (lane & 3) * 2;
            float v0 = acc[mi][nj][0], v1 = acc[mi][nj][1];
            float v2 = acc[mi][nj][2], v3 = acc[mi][nj][3];
            if (isV) {
                v0 += bias[r0];     v1 += bias[r0];
                v2 += bias[r0 + 8]; v3 += bias[r0 + 8];
            } else {
                const float b0 = bias[c0], b1 = bias[c0 + 1];
                v0 += b0; v1 += b1; v2 += b0; v3 += b1;
            }
            *(uint32_t*)(Ch + (size_t)r0 * ldc + c0)       = pack_h2(v0, v1);
            *(uint32_t*)(Ch + (size_t)(r0 + 8) * ldc + c0) = pack_h2(v2, v3);
        }
    }
}

// ---------------------------------------------------------------------------
// Proj GEMM: out = pw @ O^T + pb + x  -> fp32 [C, HW]
// ---------------------------------------------------------------------------
__global__ void __launch_bounds__(256, 2) gemm_proj(
    const fp16* __restrict__ A, const fp16* __restrict__ B,
    const float* __restrict__ bias, const float* __restrict__ resid,
    float* __restrict__ Cf, int K, int lda, int ldb, int ldc)
{
    extern __shared__ char smem[];
    const uint32_t sb = smem_u32(smem);
    const int tid  = threadIdx.x;
    const int lane = tid & 31, warp = tid >> 5;
    const int wm = (warp >> 2) * 64;
    const int wn = (warp & 3) * 32;
    const int bm = blockIdx.y * 128;
    const int bn = blockIdx.x * 128;

    float acc[4][4][4];
#pragma unroll
    for (int i = 0; i < 4; i++)
#pragma unroll
        for (int j = 0; j < 4; j++) {
            acc[i][j][0] = 0.f; acc[i][j][1] = 0.f;
            acc[i][j][2] = 0.f; acc[i][j][3] = 0.f;
        }

    const int NCH = K >> 6;
    load_stage(sb + STG_A(0), sb + STG_B(0), A, B, bm, bn, lda, ldb, 0,  tid);
    cp_commit();
    load_stage(sb + STG_A(1), sb + STG_B(1), A, B, bm, bn, lda, ldb, 64, tid);
    cp_commit();

    const int lr  = lane & 7;
    const int sel = lane >> 3;
    const int a_row  = wm + lr + (sel & 1) * 8;
    const int a_kb   = (sel >> 1) * 16;
    const int b_row0 = wn + lr + ((sel >> 1) & 1) * 8;
    const int b_kb   = (sel & 1) * 16;

#pragma unroll 1
    for (int c = 0; c < NCH; ++c) {
        CP_WAIT1();
        __syncthreads();
        const int cn = c + 2;
        if (cn < NCH)
            load_stage(sb + STG_A(cn % 3), sb + STG_B(cn % 3), A, B,
                       bm, bn, lda, ldb, cn << 6, tid);
        cp_commit();

        const uint32_t sA = sb + STG_A(c % 3);
        const uint32_t sB = sb + STG_B(c % 3);
#pragma unroll
        for (int kk = 0; kk < 4; ++kk) {
            uint32_t af[4][4], bfr[2][4];
#pragma unroll
            for (int mi = 0; mi < 4; ++mi)
                ldm_x4(af[mi], sA + SWZ(((a_row + mi * 16) << 7) + kk * 32 + a_kb));
#pragma unroll
            for (int nj = 0; nj < 2; ++nj)
                ldm_x4(bfr[nj], sB + SWZ(((b_row0 + nj * 16) << 7) + kk * 32 + b_kb));
#pragma unroll
            for (int mi = 0; mi < 4; ++mi)
#pragma unroll
                for (int nj = 0; nj < 4; ++nj)
                    mma16816(acc[mi][nj], af[mi],
                             bfr[nj >> 1][(nj & 1) * 2], bfr[nj >> 1][(nj & 1) * 2 + 1]);
        }
    }

#pragma unroll
    for (int mi = 0; mi < 4; ++mi) {
#pragma unroll
        for (int nj = 0; nj < 4; ++nj) {
            const int r0 = bm + wm + mi * 16 + (lane >> 2);
            const int c0 = bn + wn + nj * 8 + (lane & 3) * 2;
            const float2 ra = *(const float2*)(resid + (size_t)r0 * ldc + c0);
            const float2 rb = *(const float2*)(resid + (size_t)(r0 + 8) * ldc + c0);
            float v0 = acc[mi][nj][0] + bias[r0] + ra.x;
            float v1 = acc[mi][nj][1] + bias[r0] + ra.y;
            float v2 = acc[mi][nj][2] + bias[r0 + 8] + rb.x;
            float v3 = acc[mi][nj][3] + bias[r0 + 8] + rb.y;
            *(float2*)(Cf + (size_t)r0 * ldc + c0)       = make_float2(v0, v1);
            *(float2*)(Cf + (size_t)(r0 + 8) * ldc + c0) = make_float2(v2, v3);
        }
    }
}

// ---------------------------------------------------------------------------
// Wide staging (128xK chunk A, 256xK chunk B)
// ---------------------------------------------------------------------------
#define W_A(s) ((s) * 16384)
#define W_B(s) (65536 + (s) * 32768)
#define WGEMM_SMEM 196608

__device__ __forceinline__ void load_stage_w(
    uint32_t sbA, uint32_t sbB,
    const fp16* __restrict__ Ap, const fp16* __restrict__ Bp,
    int bm, int bn, int lda, int ldb, int k0, int tid)
{
#pragma unroll
    for (int r = 0; r < 4; r++) {
        const int idx = tid + (r << 8);
        const int row = idx >> 3, c8 = idx & 7;
        const uint32_t off = SWZ((row << 7) + (c8 << 4));
        cp_async16(sbA + off, Ap + (size_t)(bm + row) * lda + k0 + (c8 << 3));
    }
#pragma unroll
    for (int r = 0; r < 8; r++) {
        const int idx = tid + (r << 8);
        const int row = idx >> 3, c8 = idx & 7;
        const uint32_t off = SWZ((row << 7) + (c8 << 4));
        cp_async16(sbB + off, Bp + (size_t)(bn + row) * ldb + k0 + (c8 << 3));
    }
}

// ---------------------------------------------------------------------------
// SCORES: 128x256 tile, fp16 accumulators (rate-probe), EPI: exp + rowparts
// ---------------------------------------------------------------------------
__global__ void __launch_bounds__(256, 1) gemm_scores(
    const fp16* __restrict__ A, const fp16* __restrict__ B,
    fp16* __restrict__ Ch, float alpha)
{
    extern __shared__ char smem[];
    const uint32_t sb = smem_u32(smem);
    const int tid  = threadIdx.x;
    const int lane = tid & 31, warp = tid >> 5;
    const int wm = (warp >> 2) * 64;
    const int wn = (warp & 3) * 64;
    const int bm = blockIdx.y * 128;
    const int bn = blockIdx.x * 256;

    uint32_t acc[4][8][2];           // fp16x2 accumulators
#pragma unroll
    for (int i = 0; i < 4; i++)
#pragma unroll
        for (int j = 0; j < 8; j++) { acc[i][j][0] = 0u; acc[i][j][1] = 0u; }

    const int NCH = CCH >> 6;        // 8
    load_stage_w(sb + W_A(0), sb + W_B(0), A, B, bm, bn, CCH, CCH, 0,   tid);
    cp_commit();
    load_stage_w(sb + W_A(1), sb + W_B(1), A, B, bm, bn, CCH, CCH, 64,  tid);
    cp_commit();
    load_stage_w(sb + W_A(2), sb + W_B(2), A, B, bm, bn, CCH, CCH, 128, tid);
    cp_commit();

    const int lr  = lane & 7;
    const int sel = lane >> 3;
    const int a_row  = wm + lr + (sel & 1) * 8;
    const int a_kb   = (sel >> 1) * 16;
    const int b_row0 = wn + lr + ((sel >> 1) & 1) * 8;
    const int b_kb   = (sel & 1) * 16;

#pragma unroll 1
    for (int c = 0; c < NCH; ++c) {
        CP_WAIT2();
        __syncthreads();
        const int cn = c + 3;
        if (cn < NCH)
            load_stage_w(sb + W_A(cn & 3), sb + W_B(cn & 3), A, B,
                         bm, bn, CCH, CCH, cn << 6, tid);
        cp_commit();

        const uint32_t sA = sb + W_A(c & 3);
        const uint32_t sB = sb + W_B(c & 3);
#pragma unroll
        for (int kk = 0; kk < 4; ++kk) {
            uint32_t af[4][4], bfr[4][4];
#pragma unroll
            for (int mi = 0; mi < 4; ++mi)
                ldm_x4(af[mi], sA + SWZ(((a_row + mi * 16) << 7) + kk * 32 + a_kb));
#pragma unroll
            for (int nb = 0; nb < 4; ++nb)
                ldm_x4(bfr[nb], sB + SWZ(((b_row0 + nb * 16) << 7) + kk * 32 + b_kb));
#pragma unroll
            for (int mi = 0; mi < 4; ++mi)
#pragma unroll
                for (int nj = 0; nj < 8; ++nj)
                    mma16816h(acc[mi][nj], af[mi],
                              bfr[nj >> 1][(nj & 1) * 2], bfr[nj >> 1][(nj & 1) * 2 + 1]);
        }
    }

    // epilogue: exp + partial row sums
    float rs0[4], rs1[4];
#pragma unroll
    for (int mi = 0; mi < 4; ++mi) { rs0[mi] = 0.f; rs1[mi] = 0.f; }
#pragma unroll
    for (int mi = 0; mi < 4; ++mi) {
        const int r0 = bm + wm + mi * 16 + (lane >> 2);
#pragma unroll
        for (int nj = 0; nj < 8; ++nj) {
            const int c0 = bn + wn + nj * 8 + (lane & 3) * 2;
            const float2 lo = h2f2(acc[mi][nj][0]);
            const float2 hi = h2f2(acc[mi][nj][1]);
            float p0 = __expf(lo.x * alpha);
            float p1 = __expf(lo.y * alpha);
            float p2 = __expf(hi.x * alpha);
            float p3 = __expf(hi.y * alpha);
            rs0[mi] += p0 + p1;
            rs1[mi] += p2 + p3;
            *(uint32_t*)(Ch + (size_t)r0 * HWN + c0)       = pack_h2(p0, p1);
            *(uint32_t*)(Ch + (size_t)(r0 + 8) * HWN + c0) = pack_h2(p2, p3);
        }
    }
#pragma unroll
    for (int mi = 0; mi < 4; ++mi) {
        rs0[mi] += __shfl_xor_sync(0xffffffffu, rs0[mi], 1);
        rs0[mi] += __shfl_xor_sync(0xffffffffu, rs0[mi], 2);
        rs1[mi] += __shfl_xor_sync(0xffffffffu, rs1[mi], 1);
        rs1[mi] += __shfl_xor_sync(0xffffffffu, rs1[mi], 2);
    }
    __syncthreads();
    float* ssum = (float*)smem;            // [128][4]
    if ((lane & 3) == 0) {
#pragma unroll
        for (int mi = 0; mi < 4; ++mi) {
            const int rl = wm + mi * 16 + (lane >> 2);
            ssum[rl * 4 + (warp & 3)]       = rs0[mi];
            ssum[(rl + 8) * 4 + (warp & 3)] = rs1[mi];
        }
    }
    __syncthreads();
    if (tid < 128) {
        const float t = ssum[tid * 4] + ssum[tid * 4 + 1] +
                        ssum[tid * 4 + 2] + ssum[tid * 4 + 3];
        g_rowpart[(size_t)blockIdx.x * HWN + bm + tid] = t;
    }
}

// ---------------------------------------------------------------------------
// AV: 128x256, fp32 acc (R10 mainloop); epilogue sums g_rowpart, normalizes
// ---------------------------------------------------------------------------
__global__ void __launch_bounds__(256, 1) gemm_av(
    const fp16* __restrict__ A, const fp16* __restrict__ B,
    fp16* __restrict__ Ch)
{
    extern __shared__ char smem[];
    const uint32_t sb = smem_u32(smem);
    const int tid  = threadIdx.x;
    const int lane = tid & 31, warp = tid >> 5;
    const int wm = (warp >> 2) * 64;
    const int wn = (warp & 3) * 64;
    const int bm = blockIdx.y * 128;
    const int bn = blockIdx.x * 256;

    float acc[4][8][4];
#pragma unroll
    for (int i = 0; i < 4; i++)
#pragma unroll
        for (int j = 0; j < 8; j++) {
            acc[i][j][0] = 0.f; acc[i][j][1] = 0.f;
            acc[i][j][2] = 0.f; acc[i][j][3] = 0.f;
        }

    const int NCH = HWN >> 6;        // 144
    load_stage_w(sb + W_A(0), sb + W_B(0), A, B, bm, bn, HWN, HWN, 0,   tid);
    cp_commit();
    load_stage_w(sb + W_A(1), sb + W_B(1), A, B, bm, bn, HWN, HWN, 64,  tid);
    cp_commit();
    load_stage_w(sb + W_A(2), sb + W_B(2), A, B, bm, bn, HWN, HWN, 128, tid);
    cp_commit();

    const int lr  = lane & 7;
    const int sel = lane >> 3;
    const int a_row  = wm + lr + (sel & 1) * 8;
    const int a_kb   = (sel >> 1) * 16;
    const int b_row0 = wn + lr + ((sel >> 1) & 1) * 8;
    const int b_kb   = (sel & 1) * 16;

#pragma unroll 1
    for (int c = 0; c < NCH; ++c) {
        CP_WAIT2();
        __syncthreads();
        const int cn = c + 3;
        if (cn < NCH)
            load_stage_w(sb + W_A(cn & 3), sb + W_B(cn & 3), A, B,
                         bm, bn, HWN, HWN, cn << 6, tid);
        cp_commit();

        const uint32_t sA = sb + W_A(c & 3);
        const uint32_t sB = sb + W_B(c & 3);
#pragma unroll
        for (int kk = 0; kk < 4; ++kk) {
            uint32_t af[4][4], bfr[4][4];
#pragma unroll
            for (int mi = 0; mi < 4; ++mi)
                ldm_x4(af[mi], sA + SWZ(((a_row + mi * 16) << 7) + kk * 32 + a_kb));
#pragma unroll
            for (int nb = 0; nb < 4; ++nb)
                ldm_x4(bfr[nb], sB + SWZ(((b_row0 + nb * 16) << 7) + kk * 32 + b_kb));
#pragma unroll
            for (int mi = 0; mi < 4; ++mi)
#pragma unroll
                for (int nj = 0; nj < 8; ++nj)
                    mma16816(acc[mi][nj], af[mi],
                             bfr[nj >> 1][(nj & 1) * 2], bfr[nj >> 1][(nj & 1) * 2 + 1]);
        }
    }

    // epilogue: 1/rowsum from g_rowpart, normalize, store
    __syncthreads();
    float* ssum = (float*)smem;
    if (tid < 128) {
        float t = 0.f;
#pragma unroll
        for (int b = 0; b < 36; b++) t += g_rowpart[b * HWN + bm + tid];
        ssum[tid] = 1.0f / t;
    }
    __syncthreads();
#pragma unroll
    for (int mi = 0; mi < 4; ++mi) {
        const int rl = wm + mi * 16 + (lane >> 2);
        const int r0 = bm + rl;
        const float d0 = ssum[rl], d1 = ssum[rl + 8];
#pragma unroll
        for (int nj = 0; nj < 8; ++nj) {
            const int c0 = bn + wn + nj * 8 + (lane & 3) * 2;
            *(uint32_t*)(Ch + (size_t)r0 * CCH + c0) =
                pack_h2(acc[mi][nj][0] * d0, acc[mi][nj][1] * d0);
            *(uint32_t*)(Ch + (size_t)(r0 + 8) * CCH + c0) =
                pack_h2(acc[mi][nj][2] * d1, acc[mi][nj][3] * d1);
        }
    }
}

// ---------------------------------------------------------------------------
// Launch
// ---------------------------------------------------------------------------
extern "C" void kernel_launch(void* const* d_in, const int* in_sizes, int n_in,
                              void* d_out, int out_size)
{
    const float* x     = (const float*)d_in[0];
    const float* gamma = (const float*)d_in[1];
    const float* beta  = (const float*)d_in[2];
    const float* qw    = (const float*)d_in[3];
    const float* qb    = (const float*)d_in[4];
    const float* kw    = (const float*)d_in[5];
    const float* kb    = (const float*)d_in[6];
    const float* vw    = (const float*)d_in[7];
    const float* vb    = (const float*)d_in[8];
    const float* pw    = (const float*)d_in[9];
    const float* pb    = (const float*)d_in[10];
    float* out = (float*)d_out;

    fp16 *s, *hn, *q, *k, *v, *o, *qwh, *kwh, *vwh, *pwh;
    cudaGetSymbolAddress((void**)&s,   g_s);
    cudaGetSymbolAddress((void**)&hn,  g_hn);
    cudaGetSymbolAddress((void**)&q,   g_q);
    cudaGetSymbolAddress((void**)&k,   g_k);
    cudaGetSymbolAddress((void**)&v,   g_v);
    cudaGetSymbolAddress((void**)&o,   g_o);
    cudaGetSymbolAddress((void**)&qwh, g_qw);
    cudaGetSymbolAddress((void**)&kwh, g_kw);
    cudaGetSymbolAddress((void**)&vwh, g_vw);
    cudaGetSymbolAddress((void**)&pwh, g_pw);

    cudaFuncSetAttribute(gemm_qkv,    cudaFuncAttributeMaxDynamicSharedMemorySize, GEMM_SMEM);
    cudaFuncSetAttribute(gemm_proj,   cudaFuncAttributeMaxDynamicSharedMemorySize, GEMM_SMEM);
    cudaFuncSetAttribute(gemm_scores, cudaFuncAttributeMaxDynamicSharedMemorySize, WGEMM_SMEM);
    cudaFuncSetAttribute(gemm_av,     cudaFuncAttributeMaxDynamicSharedMemorySize, WGEMM_SMEM);

    gn_stats_kernel<<<NG, 256>>>(x);
    gn_apply_t_kernel<<<dim3(HWN / 32, CCH / 32), dim3(32, 8)>>>(x, gamma, beta, hn);
    cvt_all_kernel<<<(CCH * CCH) / 256, 256>>>(qw, qwh, kw, kwh, vw, vwh, pw, pwh);

    const float scale = 0.04419417382415922f;  // 512^-0.5

    // Q, K, V in one launch
    gemm_qkv<<<dim3(4, 72, 3), 256, GEMM_SMEM>>>(hn, qwh, kwh, vwh, qb, kb, vb, q, k, v);

    // P = exp(scale * Q @ K^T) -> fp16 [HW, HW] + partial row sums  (fp16 acc)
    gemm_scores<<<dim3(36, 72), 256, WGEMM_SMEM>>>(q, k, s, scale);

    // O = (P @ V^T) / rowsum(P) -> fp16 [HW, C]
    gemm_av<<<dim3(2, 72), 256, WGEMM_SMEM>>>(s, v, o);

    // out = pw @ O^T + pb + x -> fp32 [C, HW]
    gemm_proj<<<dim3(72, 4), 256, GEMM_SMEM>>>(pwh, o, pb, x, out, CCH, CCH, CCH, HWN);
}

// round 17
// speedup vs baseline: 1.0376x; 1.0376x over previous
#include <cuda_runtime.h>
#include <cuda_fp16.h>
#include <math.h>
#include <stdint.h>

#define HWN 9216
#define CCH 512
#define NG  32
#define CPG 16

typedef __half fp16;

// ---- scratch (static device globals) ----
__device__ fp16  g_s [(size_t)HWN * HWN];          // P = exp(scores), fp16 (170 MB)
__device__ fp16  g_hn[(size_t)HWN * CCH];
__device__ fp16  g_q [(size_t)HWN * CCH];
__device__ fp16  g_k [(size_t)HWN * CCH];
__device__ fp16  g_v [(size_t)CCH * HWN];          // v, [C, HW]
__device__ fp16  g_o [(size_t)HWN * CCH];
__device__ fp16  g_qw[CCH * CCH], g_kw[CCH * CCH];
__device__ fp16  g_vw[CCH * CCH], g_pw[CCH * CCH];
__device__ float g_rowpart[36 * HWN];
__device__ float g_stats[NG * 2];

// ---------------------------------------------------------------------------
// helpers
// ---------------------------------------------------------------------------
__device__ __forceinline__ uint32_t smem_u32(const void* p) {
    uint32_t a;
    asm("{ .reg .u64 t; cvta.to.shared.u64 t, %1; cvt.u32.u64 %0, t; }" : "=r"(a) : "l"(p));
    return a;
}
#define SWZ(x) ((x) ^ (((x) >> 3) & 0x70))

__device__ __forceinline__ void cp_async16(uint32_t saddr, const void* gaddr) {
    asm volatile("cp.async.cg.shared.global [%0], [%1], 16;" :: "r"(saddr), "l"(gaddr));
}
__device__ __forceinline__ void cp_commit() { asm volatile("cp.async.commit_group;"); }
#define CP_WAIT0() asm volatile("cp.async.wait_group 0;")
#define CP_WAIT1() asm volatile("cp.async.wait_group 1;")

__device__ __forceinline__ void ldm_x4(uint32_t* r, uint32_t addr) {
    asm volatile("ldmatrix.sync.aligned.m8n8.x4.shared.b16 {%0,%1,%2,%3}, [%4];"
                 : "=r"(r[0]), "=r"(r[1]), "=r"(r[2]), "=r"(r[3]) : "r"(addr));
}
__device__ __forceinline__ void mma16816(float* d, const uint32_t* a, uint32_t b0, uint32_t b1) {
    asm volatile(
        "mma.sync.aligned.m16n8k16.row.col.f32.f16.f16.f32 "
        "{%0,%1,%2,%3}, {%4,%5,%6,%7}, {%8,%9}, {%0,%1,%2,%3};"
        : "+f"(d[0]), "+f"(d[1]), "+f"(d[2]), "+f"(d[3])
        : "r"(a[0]), "r"(a[1]), "r"(a[2]), "r"(a[3]), "r"(b0), "r"(b1));
}

__device__ __forceinline__ uint32_t pack_h2(float a, float b) {
    __half2 h = __floats2half2_rn(a, b);
    return *(uint32_t*)&h;
}

// ---------------------------------------------------------------------------
// GroupNorm stats
// ---------------------------------------------------------------------------
__global__ void gn_stats_kernel(const float* __restrict__ x) {
    const int g = blockIdx.x;
    const float4* xp = (const float4*)(x + (size_t)g * CPG * HWN);
    const int n4 = (CPG * HWN) / 4;
    float s = 0.f, s2 = 0.f;
    for (int i = threadIdx.x; i < n4; i += 256) {
        float4 v = xp[i];
        s  += v.x + v.y + v.z + v.w;
        s2 += v.x * v.x + v.y * v.y + v.z * v.z + v.w * v.w;
    }
    __shared__ float rs[256], rq[256];
    rs[threadIdx.x] = s; rq[threadIdx.x] = s2;
    __syncthreads();
    for (int o = 128; o > 0; o >>= 1) {
        if (threadIdx.x < o) {
            rs[threadIdx.x] += rs[threadIdx.x + o];
            rq[threadIdx.x] += rq[threadIdx.x + o];
        }
        __syncthreads();
    }
    if (threadIdx.x == 0) {
        const float inv  = 1.0f / (float)(CPG * HWN);
        const float mean = rs[0] * inv;
        const float var  = rq[0] * inv - mean * mean;
        g_stats[2 * g]     = mean;
        g_stats[2 * g + 1] = rsqrtf(var + 1e-6f);
    }
}

// ---------------------------------------------------------------------------
// GroupNorm apply + transpose: x [C, HW] -> hn fp16 [HW, C]
// ---------------------------------------------------------------------------
__global__ void gn_apply_t_kernel(const float* __restrict__ x,
                                  const float* __restrict__ gamma,
                                  const float* __restrict__ beta,
                                  fp16* __restrict__ out) {
    __shared__ float t[32][33];
    const int i0 = blockIdx.x * 32, c0 = blockIdx.y * 32;
    const int tx = threadIdx.x, ty = threadIdx.y;
#pragma unroll
    for (int k = 0; k < 32; k += 8) {
        const int c = c0 + ty + k;
        const int g = c >> 4;
        const float mean = g_stats[2 * g], rstd = g_stats[2 * g + 1];
        const float ga = gamma[c] * rstd;
        const float be = beta[c] - mean * ga;
        t[ty + k][tx] = x[(size_t)c * HWN + i0 + tx] * ga + be;
    }
    __syncthreads();
#pragma unroll
    for (int k = 0; k < 32; k += 8)
        out[(size_t)(i0 + ty + k) * CCH + c0 + tx] = __float2half(t[tx][ty + k]);
}

__global__ void cvt_all_kernel(const float* __restrict__ w0, fp16* __restrict__ h0,
                               const float* __restrict__ w1, fp16* __restrict__ h1,
                               const float* __restrict__ w2, fp16* __restrict__ h2,
                               const float* __restrict__ w3, fp16* __restrict__ h3) {
    const int i = blockIdx.x * 256 + threadIdx.x;
    h0[i] = __float2half(w0[i]);
    h1[i] = __float2half(w1[i]);
    h2[i] = __float2half(w2[i]);
    h3[i] = __float2half(w3[i]);
}

// ---------------------------------------------------------------------------
// Staging helper (narrow GEMMs): 128 rows x 64 halves per operand
// ---------------------------------------------------------------------------
#define STG_A(s) ((s) * 16384)
#define STG_B(s) (49152 + (s) * 16384)
#define GEMM_SMEM 98304

__device__ __forceinline__ void load_stage(
    uint32_t sbA, uint32_t sbB,
    const fp16* __restrict__ Ap, const fp16* __restrict__ Bp,
    int bm, int bn, int lda, int ldb, int k0, int tid)
{
#pragma unroll
    for (int r = 0; r < 4; r++) {
        const int idx = tid + (r << 8);
        const int row = idx >> 3, c8 = idx & 7;
        const uint32_t off = SWZ((row << 7) + (c8 << 4));
        cp_async16(sbA + off, Ap + (size_t)(bm + row) * lda + k0 + (c8 << 3));
        cp_async16(sbB + off, Bp + (size_t)(bn + row) * ldb + k0 + (c8 << 3));
    }
}

// ---------------------------------------------------------------------------
// Fused QKV GEMM (one launch, grid (4,72,3))
// ---------------------------------------------------------------------------
__global__ void __launch_bounds__(256, 2) gemm_qkv(
    const fp16* __restrict__ hn,
    const fp16* __restrict__ qwh, const fp16* __restrict__ kwh, const fp16* __restrict__ vwh,
    const float* __restrict__ qb, const float* __restrict__ kb, const float* __restrict__ vb,
    fp16* __restrict__ q, fp16* __restrict__ k, fp16* __restrict__ v)
{
    const int z = blockIdx.z;
    const bool isV = (z == 2);
    const fp16* A = isV ? vwh : hn;
    const fp16* B = isV ? hn : (z ? kwh : qwh);
    const float* bias = isV ? vb : (z ? kb : qb);
    fp16* Ch = isV ? v : (z ? k : q);
    const int ldc = isV ? HWN : CCH;
    const int bm = (isV ? blockIdx.x : blockIdx.y) * 128;
    const int bn = (isV ? blockIdx.y : blockIdx.x) * 128;

    extern __shared__ char smem[];
    const uint32_t sb = smem_u32(smem);
    const int tid  = threadIdx.x;
    const int lane = tid & 31, warp = tid >> 5;
    const int wm = (warp >> 2) * 64;
    const int wn = (warp & 3) * 32;

    float acc[4][4][4];
#pragma unroll
    for (int i = 0; i < 4; i++)
#pragma unroll
        for (int j = 0; j < 4; j++) {
            acc[i][j][0] = 0.f; acc[i][j][1] = 0.f;
            acc[i][j][2] = 0.f; acc[i][j][3] = 0.f;
        }

    const int NCH = CCH >> 6;   // 8
    load_stage(sb + STG_A(0), sb + STG_B(0), A, B, bm, bn, CCH, CCH, 0,  tid);
    cp_commit();
    load_stage(sb + STG_A(1), sb + STG_B(1), A, B, bm, bn, CCH, CCH, 64, tid);
    cp_commit();

    const int lr  = lane & 7;
    const int sel = lane >> 3;
    const int a_row  = wm + lr + (sel & 1) * 8;
    const int a_kb   = (sel >> 1) * 16;
    const int b_row0 = wn + lr + ((sel >> 1) & 1) * 8;
    const int b_kb   = (sel & 1) * 16;

#pragma unroll 1
    for (int c = 0; c < NCH; ++c) {
        CP_WAIT1();
        __syncthreads();
        const int cn = c + 2;
        if (cn < NCH)
            load_stage(sb + STG_A(cn % 3), sb + STG_B(cn % 3), A, B,
                       bm, bn, CCH, CCH, cn << 6, tid);
        cp_commit();

        const uint32_t sA = sb + STG_A(c % 3);
        const uint32_t sB = sb + STG_B(c % 3);
#pragma unroll
        for (int kk = 0; kk < 4; ++kk) {
            uint32_t af[4][4], bfr[2][4];
#pragma unroll
            for (int mi = 0; mi < 4; ++mi)
                ldm_x4(af[mi], sA + SWZ(((a_row + mi * 16) << 7) + kk * 32 + a_kb));
#pragma unroll
            for (int nj = 0; nj < 2; ++nj)
                ldm_x4(bfr[nj], sB + SWZ(((b_row0 + nj * 16) << 7) + kk * 32 + b_kb));
#pragma unroll
            for (int mi = 0; mi < 4; ++mi)
#pragma unroll
                for (int nj = 0; nj < 4; ++nj)
                    mma16816(acc[mi][nj], af[mi],
                             bfr[nj >> 1][(nj & 1) * 2], bfr[nj >> 1][(nj & 1) * 2 + 1]);
        }
    }

#pragma unroll
    for (int mi = 0; mi < 4; ++mi) {
#pragma unroll
        for (int nj = 0; nj < 4; ++nj) {
            const int r0 = bm + wm + mi * 16 + (lane >> 2);
            const int c0 = bn + wn + nj * 8 + (lane & 3) * 2;
            float v0 = acc[mi][nj][0], v1 = acc[mi][nj][1];
            float v2 = acc[mi][nj][2], v3 = acc[mi][nj][3];
            if (isV) {
                v0 += bias[r0];     v1 += bias[r0];
                v2 += bias[r0 + 8]; v3 += bias[r0 + 8];
            } else {
                const float b0 = bias[c0], b1 = bias[c0 + 1];
                v0 += b0; v1 += b1; v2 += b0; v3 += b1;
            }
            *(uint32_t*)(Ch + (size_t)r0 * ldc + c0)       = pack_h2(v0, v1);
            *(uint32_t*)(Ch + (size_t)(r0 + 8) * ldc + c0) = pack_h2(v2, v3);
        }
    }
}

// ---------------------------------------------------------------------------
// Proj GEMM: out = pw @ O^T + pb + x  -> fp32 [C, HW]
// ---------------------------------------------------------------------------
__global__ void __launch_bounds__(256, 2) gemm_proj(
    const fp16* __restrict__ A, const fp16* __restrict__ B,
    const float* __restrict__ bias, const float* __restrict__ resid,
    float* __restrict__ Cf, int K, int lda, int ldb, int ldc)
{
    extern __shared__ char smem[];
    const uint32_t sb = smem_u32(smem);
    const int tid  = threadIdx.x;
    const int lane = tid & 31, warp = tid >> 5;
    const int wm = (warp >> 2) * 64;
    const int wn = (warp & 3) * 32;
    const int bm = blockIdx.y * 128;
    const int bn = blockIdx.x * 128;

    float acc[4][4][4];
#pragma unroll
    for (int i = 0; i < 4; i++)
#pragma unroll
        for (int j = 0; j < 4; j++) {
            acc[i][j][0] = 0.f; acc[i][j][1] = 0.f;
            acc[i][j][2] = 0.f; acc[i][j][3] = 0.f;
        }

    const int NCH = K >> 6;
    load_stage(sb + STG_A(0), sb + STG_B(0), A, B, bm, bn, lda, ldb, 0,  tid);
    cp_commit();
    load_stage(sb + STG_A(1), sb + STG_B(1), A, B, bm, bn, lda, ldb, 64, tid);
    cp_commit();

    const int lr  = lane & 7;
    const int sel = lane >> 3;
    const int a_row  = wm + lr + (sel & 1) * 8;
    const int a_kb   = (sel >> 1) * 16;
    const int b_row0 = wn + lr + ((sel >> 1) & 1) * 8;
    const int b_kb   = (sel & 1) * 16;

#pragma unroll 1
    for (int c = 0; c < NCH; ++c) {
        CP_WAIT1();
        __syncthreads();
        const int cn = c + 2;
        if (cn < NCH)
            load_stage(sb + STG_A(cn % 3), sb + STG_B(cn % 3), A, B,
                       bm, bn, lda, ldb, cn << 6, tid);
        cp_commit();

        const uint32_t sA = sb + STG_A(c % 3);
        const uint32_t sB = sb + STG_B(c % 3);
#pragma unroll
        for (int kk = 0; kk < 4; ++kk) {
            uint32_t af[4][4], bfr[2][4];
#pragma unroll
            for (int mi = 0; mi < 4; ++mi)
                ldm_x4(af[mi], sA + SWZ(((a_row + mi * 16) << 7) + kk * 32 + a_kb));
#pragma unroll
            for (int nj = 0; nj < 2; ++nj)
                ldm_x4(bfr[nj], sB + SWZ(((b_row0 + nj * 16) << 7) + kk * 32 + b_kb));
#pragma unroll
            for (int mi = 0; mi < 4; ++mi)
#pragma unroll
                for (int nj = 0; nj < 4; ++nj)
                    mma16816(acc[mi][nj], af[mi],
                             bfr[nj >> 1][(nj & 1) * 2], bfr[nj >> 1][(nj & 1) * 2 + 1]);
        }
    }

#pragma unroll
    for (int mi = 0; mi < 4; ++mi) {
#pragma unroll
        for (int nj = 0; nj < 4; ++nj) {
            const int r0 = bm + wm + mi * 16 + (lane >> 2);
            const int c0 = bn + wn + nj * 8 + (lane & 3) * 2;
            const float2 ra = *(const float2*)(resid + (size_t)r0 * ldc + c0);
            const float2 rb = *(const float2*)(resid + (size_t)(r0 + 8) * ldc + c0);
            float v0 = acc[mi][nj][0] + bias[r0] + ra.x;
            float v1 = acc[mi][nj][1] + bias[r0] + ra.y;
            float v2 = acc[mi][nj][2] + bias[r0 + 8] + rb.x;
            float v3 = acc[mi][nj][3] + bias[r0 + 8] + rb.y;
            *(float2*)(Cf + (size_t)r0 * ldc + c0)       = make_float2(v0, v1);
            *(float2*)(Cf + (size_t)(r0 + 8) * ldc + c0) = make_float2(v2, v3);
        }
    }
}

// ---------------------------------------------------------------------------
// Wide GEMM: 128x256 tile, BK=128 chunk (2 x 64-wide subtiles), 2-stage
// double buffer. SMEM: 2 x (32KB A + 64KB B) = 192 KB, 1 CTA/SM.
// EPI 6 = P = exp(alpha*s) + partial row sums    EPI 5 = AV + normalize
// ---------------------------------------------------------------------------
#define W2A(s, t) ((s) * 32768 + (t) * 16384)
#define W2B(s, t) (65536 + (s) * 65536 + (t) * 32768)
#define WGEMM_SMEM 196608

// load one 64-wide subtile pair (A 128 rows, B 256 rows)
__device__ __forceinline__ void load_sub_w(
    uint32_t sbA, uint32_t sbB,
    const fp16* __restrict__ Ap, const fp16* __restrict__ Bp,
    int bm, int bn, int lda, int ldb, int k0, int tid)
{
#pragma unroll
    for (int r = 0; r < 4; r++) {
        const int idx = tid + (r << 8);
        const int row = idx >> 3, c8 = idx & 7;
        const uint32_t off = SWZ((row << 7) + (c8 << 4));
        cp_async16(sbA + off, Ap + (size_t)(bm + row) * lda + k0 + (c8 << 3));
    }
#pragma unroll
    for (int r = 0; r < 8; r++) {
        const int idx = tid + (r << 8);
        const int row = idx >> 3, c8 = idx & 7;
        const uint32_t off = SWZ((row << 7) + (c8 << 4));
        cp_async16(sbB + off, Bp + (size_t)(bn + row) * ldb + k0 + (c8 << 3));
    }
}

__device__ __forceinline__ void load_chunk_w(
    uint32_t sb, int s,
    const fp16* __restrict__ Ap, const fp16* __restrict__ Bp,
    int bm, int bn, int lda, int ldb, int k0, int tid)
{
    load_sub_w(sb + W2A(s, 0), sb + W2B(s, 0), Ap, Bp, bm, bn, lda, ldb, k0,      tid);
    load_sub_w(sb + W2A(s, 1), sb + W2B(s, 1), Ap, Bp, bm, bn, lda, ldb, k0 + 64, tid);
}

template <int EPI>
__global__ void __launch_bounds__(256, 1) gemm_fp16_w(
    const fp16* __restrict__ A, const fp16* __restrict__ B,
    fp16* __restrict__ Ch, int K, int lda, int ldb, int ldc, float alpha)
{
    extern __shared__ char smem[];
    const uint32_t sb = smem_u32(smem);
    const int tid  = threadIdx.x;
    const int lane = tid & 31, warp = tid >> 5;
    const int wm = (warp >> 2) * 64;
    const int wn = (warp & 3) * 64;
    const int bm = blockIdx.y * 128;
    const int bn = blockIdx.x * 256;

    float acc[4][8][4];
#pragma unroll
    for (int i = 0; i < 4; i++)
#pragma unroll
        for (int j = 0; j < 8; j++) {
            acc[i][j][0] = 0.f; acc[i][j][1] = 0.f;
            acc[i][j][2] = 0.f; acc[i][j][3] = 0.f;
        }

    const int NC2 = K >> 7;   // chunks of 128
    load_chunk_w(sb, 0, A, B, bm, bn, lda, ldb, 0, tid);
    cp_commit();

    const int lr  = lane & 7;
    const int sel = lane >> 3;
    const int a_row  = wm + lr + (sel & 1) * 8;
    const int a_kb   = (sel >> 1) * 16;
    const int b_row0 = wn + lr + ((sel >> 1) & 1) * 8;
    const int b_kb   = (sel & 1) * 16;

#pragma unroll 1
    for (int c = 0; c < NC2; ++c) {
        CP_WAIT0();
        __syncthreads();
        if (c + 1 < NC2)
            load_chunk_w(sb, (c + 1) & 1, A, B, bm, bn, lda, ldb, (c + 1) << 7, tid);
        cp_commit();

#pragma unroll
        for (int t = 0; t < 2; ++t) {
            const uint32_t sA = sb + W2A(c & 1, t);
            const uint32_t sB = sb + W2B(c & 1, t);
#pragma unroll
            for (int kk = 0; kk < 4; ++kk) {
                uint32_t af[4][4], bfr[4][4];
#pragma unroll
                for (int mi = 0; mi < 4; ++mi)
                    ldm_x4(af[mi], sA + SWZ(((a_row + mi * 16) << 7) + kk * 32 + a_kb));
#pragma unroll
                for (int nb = 0; nb < 4; ++nb)
                    ldm_x4(bfr[nb], sB + SWZ(((b_row0 + nb * 16) << 7) + kk * 32 + b_kb));
#pragma unroll
                for (int mi = 0; mi < 4; ++mi)
#pragma unroll
                    for (int nj = 0; nj < 8; ++nj)
                        mma16816(acc[mi][nj], af[mi],
                                 bfr[nj >> 1][(nj & 1) * 2], bfr[nj >> 1][(nj & 1) * 2 + 1]);
            }
        }
    }

    if (EPI == 6) {
        float rs0[4], rs1[4];
#pragma unroll
        for (int mi = 0; mi < 4; ++mi) { rs0[mi] = 0.f; rs1[mi] = 0.f; }
#pragma unroll
        for (int mi = 0; mi < 4; ++mi) {
            const int r0 = bm + wm + mi * 16 + (lane >> 2);
#pragma unroll
            for (int nj = 0; nj < 8; ++nj) {
                const int c0 = bn + wn + nj * 8 + (lane & 3) * 2;
                float p0 = __expf(acc[mi][nj][0] * alpha);
                float p1 = __expf(acc[mi][nj][1] * alpha);
                float p2 = __expf(acc[mi][nj][2] * alpha);
                float p3 = __expf(acc[mi][nj][3] * alpha);
                rs0[mi] += p0 + p1;
                rs1[mi] += p2 + p3;
                *(uint32_t*)(Ch + (size_t)r0 * ldc + c0)       = pack_h2(p0, p1);
                *(uint32_t*)(Ch + (size_t)(r0 + 8) * ldc + c0) = pack_h2(p2, p3);
            }
        }
#pragma unroll
        for (int mi = 0; mi < 4; ++mi) {
            rs0[mi] += __shfl_xor_sync(0xffffffffu, rs0[mi], 1);
            rs0[mi] += __shfl_xor_sync(0xffffffffu, rs0[mi], 2);
            rs1[mi] += __shfl_xor_sync(0xffffffffu, rs1[mi], 1);
            rs1[mi] += __shfl_xor_sync(0xffffffffu, rs1[mi], 2);
        }
        __syncthreads();
        float* ssum = (float*)smem;            // [128][4]
        if ((lane & 3) == 0) {
#pragma unroll
            for (int mi = 0; mi < 4; ++mi) {
                const int rl = wm + mi * 16 + (lane >> 2);
                ssum[rl * 4 + (warp & 3)]       = rs0[mi];
                ssum[(rl + 8) * 4 + (warp & 3)] = rs1[mi];
            }
        }
        __syncthreads();
        if (tid < 128) {
            const float t = ssum[tid * 4] + ssum[tid * 4 + 1] +
                            ssum[tid * 4 + 2] + ssum[tid * 4 + 3];
            g_rowpart[(size_t)blockIdx.x * HWN + bm + tid] = t;
        }
    } else {
        // AV: 1/rowsum from g_rowpart, normalize, store
        __syncthreads();
        float* ssum = (float*)smem;
        if (tid < 128) {
            float t = 0.f;
#pragma unroll
            for (int b = 0; b < 36; b++) t += g_rowpart[b * HWN + bm + tid];
            ssum[tid] = 1.0f / t;
        }
        __syncthreads();
#pragma unroll
        for (int mi = 0; mi < 4; ++mi) {
            const int rl = wm + mi * 16 + (lane >> 2);
            const int r0 = bm + rl;
            const float d0 = ssum[rl], d1 = ssum[rl + 8];
#pragma unroll
            for (int nj = 0; nj < 8; ++nj) {
                const int c0 = bn + wn + nj * 8 + (lane & 3) * 2;
                *(uint32_t*)(Ch + (size_t)r0 * ldc + c0) =
                    pack_h2(acc[mi][nj][0] * d0, acc[mi][nj][1] * d0);
                *(uint32_t*)(Ch + (size_t)(r0 + 8) * ldc + c0) =
                    pack_h2(acc[mi][nj][2] * d1, acc[mi][nj][3] * d1);
            }
        }
    }
}

// ---------------------------------------------------------------------------
// Launch
// ---------------------------------------------------------------------------
extern "C" void kernel_launch(void* const* d_in, const int* in_sizes, int n_in,
                              void* d_out, int out_size)
{
    const float* x     = (const float*)d_in[0];
    const float* gamma = (const float*)d_in[1];
    const float* beta  = (const float*)d_in[2];
    const float* qw    = (const float*)d_in[3];
    const float* qb    = (const float*)d_in[4];
    const float* kw    = (const float*)d_in[5];
    const float* kb    = (const float*)d_in[6];
    const float* vw    = (const float*)d_in[7];
    const float* vb    = (const float*)d_in[8];
    const float* pw    = (const float*)d_in[9];
    const float* pb    = (const float*)d_in[10];
    float* out = (float*)d_out;

    fp16 *s, *hn, *q, *k, *v, *o, *qwh, *kwh, *vwh, *pwh;
    cudaGetSymbolAddress((void**)&s,   g_s);
    cudaGetSymbolAddress((void**)&hn,  g_hn);
    cudaGetSymbolAddress((void**)&q,   g_q);
    cudaGetSymbolAddress((void**)&k,   g_k);
    cudaGetSymbolAddress((void**)&v,   g_v);
    cudaGetSymbolAddress((void**)&o,   g_o);
    cudaGetSymbolAddress((void**)&qwh, g_qw);
    cudaGetSymbolAddress((void**)&kwh, g_kw);
    cudaGetSymbolAddress((void**)&vwh, g_vw);
    cudaGetSymbolAddress((void**)&pwh, g_pw);

    cudaFuncSetAttribute(gemm_qkv,  cudaFuncAttributeMaxDynamicSharedMemorySize, GEMM_SMEM);
    cudaFuncSetAttribute(gemm_proj, cudaFuncAttributeMaxDynamicSharedMemorySize, GEMM_SMEM);
    cudaFuncSetAttribute(gemm_fp16_w<5>, cudaFuncAttributeMaxDynamicSharedMemorySize, WGEMM_SMEM);
    cudaFuncSetAttribute(gemm_fp16_w<6>, cudaFuncAttributeMaxDynamicSharedMemorySize, WGEMM_SMEM);

    gn_stats_kernel<<<NG, 256>>>(x);
    gn_apply_t_kernel<<<dim3(HWN / 32, CCH / 32), dim3(32, 8)>>>(x, gamma, beta, hn);
    cvt_all_kernel<<<(CCH * CCH) / 256, 256>>>(qw, qwh, kw, kwh, vw, vwh, pw, pwh);

    const float scale = 0.04419417382415922f;  // 512^-0.5

    // Q, K, V in one launch
    gemm_qkv<<<dim3(4, 72, 3), 256, GEMM_SMEM>>>(hn, qwh, kwh, vwh, qb, kb, vb, q, k, v);

    // P = exp(scale * Q @ K^T) -> fp16 [HW, HW] + partial row sums
    gemm_fp16_w<6><<<dim3(36, 72), 256, WGEMM_SMEM>>>(q, k, s, CCH, CCH, CCH, HWN, scale);

    // O = (P @ V^T) / rowsum(P) -> fp16 [HW, C]
    gemm_fp16_w<5><<<dim3(2, 72), 256, WGEMM_SMEM>>>(s, v, o, HWN, HWN, HWN, CCH, 0.f);

    // out = pw @ O^T + pb + x -> fp32 [C, HW]
    gemm_proj<<<dim3(72, 4), 256, GEMM_SMEM>>>(pwh, o, pb, x, out, CCH, CCH, CCH, HWN);
}